// round 17
// baseline (speedup 1.0000x reference)
#include <cuda_runtime.h>

#define RR 256
#define TT 32
#define BB 32
#define YSZ 64

#define TILE 64
#define XS 68      // x tile with halo 2 on each side
#define HS 66      // conv1 output tile (halo 1 for conv2)
#define HSTR 68    // padded stride for 16B-aligned float4 loads
#define CH 3       // channels per hs pass (R17: 73.2 KB smem -> 3 CTAs/SM)
#define NGRP 11    // 33 channel slots; slot 32 is a zeroed dummy

#define XS_FLOATS   (XS * XS)          // 4624
#define HS_FLOATS   (HS * HSTR)        // 4488
#define SMEM_FLOATS (XS_FLOATS + CH * HS_FLOATS + 297 + 297 + 33 + 1)
#define SMEM_BYTES  (SMEM_FLOATS * 4)  // 74864 -> 3 CTAs/SM

// 8MB scratch for stage-1 output (device global: no allocation)
__device__ float g_x[BB * RR * RR];

// ---------------------------------------------------------------------------
// Stage 1: x[b,p,q] = sum_t Ht[t,p,q] * yt[b,t,p>>2,q>>2]
// 4 p-rows per CTA (share yr=p>>2) -> one yt smem fill serves 4x work.
// Grid: (64, 8). 256 threads = q.
// ---------------------------------------------------------------------------
__global__ __launch_bounds__(256) void stage1_kernel(
    const float* __restrict__ yt, const float* __restrict__ Ht)
{
    __shared__ float s_yt[4][TT][YSZ];   // 32 KB

    const int yr  = blockIdx.x;          // 0..63; serves p = 4*yr .. 4*yr+3
    const int bg  = blockIdx.y;          // group of 4 batches
    const int tid = threadIdx.x;

    for (int i = tid; i < 4 * TT * YSZ; i += 256) {
        int q4 = i & 63;
        int t  = (i >> 6) & 31;
        int bl = i >> 11;
        s_yt[bl][t][q4] = yt[(((bg * 4 + bl) * TT + t) * YSZ + yr) * YSZ + q4];
    }
    __syncthreads();

    const int q  = tid;
    const int q4 = q >> 2;
    const float* hbase = Ht + (yr * 4) * RR + q;   // Ht[t, 4*yr + pp, q]

    float a[4][4];   // [pp][bl]
#pragma unroll
    for (int pp = 0; pp < 4; pp++)
#pragma unroll
        for (int bl = 0; bl < 4; bl++) a[pp][bl] = 0.f;

#pragma unroll 8
    for (int t = 0; t < TT; t++) {
        float y0 = s_yt[0][t][q4];
        float y1 = s_yt[1][t][q4];
        float y2 = s_yt[2][t][q4];
        float y3 = s_yt[3][t][q4];
#pragma unroll
        for (int pp = 0; pp < 4; pp++) {
            float h = hbase[t * RR * RR + pp * RR];
            a[pp][0] = fmaf(h, y0, a[pp][0]);
            a[pp][1] = fmaf(h, y1, a[pp][1]);
            a[pp][2] = fmaf(h, y2, a[pp][2]);
            a[pp][3] = fmaf(h, y3, a[pp][3]);
        }
    }
#pragma unroll
    for (int pp = 0; pp < 4; pp++)
#pragma unroll
        for (int bl = 0; bl < 4; bl++)
            g_x[(bg * 4 + bl) * RR * RR + (yr * 4 + pp) * RR + q] = a[pp][bl];
}

// ---------------------------------------------------------------------------
// Conv(1->32,3x3) -> ReLU -> Conv(32->1,3x3), fused, CH=3 per pass
// (11 groups over 33 channel slots; slot 32 has zeroed weights).
// conv1: 3-row x 2-col walks, float2 taps/stores. conv2: 4x4 reg tile.
// Grid: (4, 4, 32). 256 threads. 73.2 KB dyn smem -> 3 CTAs/SM.
// ---------------------------------------------------------------------------
__global__ __launch_bounds__(256, 3) void conv_fused_kernel(
    const float* __restrict__ W1, const float* __restrict__ b1,
    const float* __restrict__ W2, const float* __restrict__ b2,
    float* __restrict__ out)
{
    extern __shared__ float smem[];
    float* xs  = smem;                        // 68x68
    float* hsb = smem + XS_FLOATS;            // CH * 66x68
    float* w1s = hsb + CH * HS_FLOATS;        // 297 (33 ch)
    float* w2s = w1s + 297;                   // 297
    float* b1s = w2s + 297;                   // 33
    float* b2s = b1s + 33;                    // 1

    const int b   = blockIdx.z;
    const int ty0 = blockIdx.y * TILE;
    const int tx0 = blockIdx.x * TILE;
    const int tid = threadIdx.x;

    // Stage 33 channels of weights; slot 32 zeroed (dummy).
    for (int i = tid; i < 297; i += 256) {
        float a1v = (i < 288) ? W1[i] : 0.f;
        float a2v = (i < 288) ? W2[i] : 0.f;
        w1s[i] = a1v; w2s[i] = a2v;
    }
    if (tid < 33) b1s[tid] = (tid < 32) ? b1[tid] : 0.f;
    if (tid == 0) b2s[0] = b2[0];

    // Load x tile with halo 2 (zero-pad at image borders)
    const float* xb = g_x + b * RR * RR;
    for (int i = tid; i < XS_FLOATS; i += 256) {
        int ry = i / XS, rx = i - ry * XS;
        int gy = ty0 - 2 + ry, gx = tx0 - 2 + rx;
        float v = 0.f;
        if (gy >= 0 && gy < RR && gx >= 0 && gx < RR) v = xb[gy * RR + gx];
        xs[i] = v;
    }
    __syncthreads();

    const int tx = tid & 15;
    const int ty = tid >> 4;
    const int ox = tx * 4;
    const int oy = ty * 4;

    float acc[4][4];
#pragma unroll
    for (int i = 0; i < 4; i++)
#pragma unroll
        for (int j = 0; j < 4; j++) acc[i][j] = 0.f;

    for (int g = 0; g < NGRP; g++) {
        const int c0 = g * CH;

        float w1r[CH][9], bcr[CH];
#pragma unroll
        for (int cc = 0; cc < CH; cc++) {
#pragma unroll
            for (int k = 0; k < 9; k++) w1r[cc][k] = w1s[(c0 + cc) * 9 + k];
            bcr[cc] = b1s[c0 + cc];
        }

        // --- conv1: 22 bands x 33 col-pairs of 3-row x 2-col walks ---
        for (int s = tid; s < 22 * 33; s += 256) {
            int band = s / 33;
            int cp   = s - band * 33;
            int col  = cp * 2;            // even: float2-aligned
            int r0   = band * 3;
            bool c0_oob = ((unsigned)(tx0 + col - 1) >= RR);
            bool c1_oob = ((unsigned)(tx0 + col)     >= RR);

            float2 A0 = *(const float2*)(xs + r0 * XS + col);
            float2 B0 = *(const float2*)(xs + r0 * XS + col + 2);
            float2 A1 = *(const float2*)(xs + (r0 + 1) * XS + col);
            float2 B1 = *(const float2*)(xs + (r0 + 1) * XS + col + 2);
            const float* xrow = xs + (r0 + 2) * XS + col;
            float* hp = hsb + r0 * HSTR + col;
            int gy = ty0 + r0 - 1;

#pragma unroll
            for (int r = 0; r < 3; r++) {
                float2 A2 = *(const float2*)(xrow);
                float2 B2 = *(const float2*)(xrow + 2);
                bool row_oob = ((unsigned)gy >= RR);
#pragma unroll
                for (int cc = 0; cc < CH; cc++) {
                    const float* w = w1r[cc];
                    float v0 = bcr[cc], v1 = bcr[cc];
                    v0 = fmaf(w[0], A0.x, v0);  v1 = fmaf(w[0], A0.y, v1);
                    v0 = fmaf(w[1], A0.y, v0);  v1 = fmaf(w[1], B0.x, v1);
                    v0 = fmaf(w[2], B0.x, v0);  v1 = fmaf(w[2], B0.y, v1);
                    v0 = fmaf(w[3], A1.x, v0);  v1 = fmaf(w[3], A1.y, v1);
                    v0 = fmaf(w[4], A1.y, v0);  v1 = fmaf(w[4], B1.x, v1);
                    v0 = fmaf(w[5], B1.x, v0);  v1 = fmaf(w[5], B1.y, v1);
                    v0 = fmaf(w[6], A2.x, v0);  v1 = fmaf(w[6], A2.y, v1);
                    v0 = fmaf(w[7], A2.y, v0);  v1 = fmaf(w[7], B2.x, v1);
                    v0 = fmaf(w[8], B2.x, v0);  v1 = fmaf(w[8], B2.y, v1);
                    v0 = (row_oob || c0_oob) ? 0.f : fmaxf(v0, 0.f);
                    v1 = (row_oob || c1_oob) ? 0.f : fmaxf(v1, 0.f);
                    *(float2*)(hp + cc * HS_FLOATS) = make_float2(v0, v1);
                }
                hp += HSTR; xrow += XS; gy++;
                A0 = A1; B0 = B1;
                A1 = A2; B1 = B2;
            }
        }
        __syncthreads();

        // --- conv2: accumulate CH channels into 4x4 register tile ---
#pragma unroll
        for (int cc = 0; cc < CH; cc++) {
            if (c0 + cc < 32) {           // uniform guard: skip dummy slot 32
                float w2r[9];
#pragma unroll
                for (int k = 0; k < 9; k++) w2r[k] = w2s[(c0 + cc) * 9 + k];
                const float* hc = hsb + cc * HS_FLOATS;
#pragma unroll
                for (int pr = 0; pr < 6; pr++) {
                    const float* hq = hc + (oy + pr) * HSTR + ox;
                    float4 v4 = *(const float4*)hq;
                    float2 v2 = *(const float2*)(hq + 4);
                    float rv[6] = { v4.x, v4.y, v4.z, v4.w, v2.x, v2.y };
#pragma unroll
                    for (int i = 0; i < 4; i++) {
                        int dy = pr - i;
                        if (dy >= 0 && dy < 3) {
#pragma unroll
                            for (int j = 0; j < 4; j++) {
                                acc[i][j] = fmaf(w2r[dy * 3 + 0], rv[j],     acc[i][j]);
                                acc[i][j] = fmaf(w2r[dy * 3 + 1], rv[j + 1], acc[i][j]);
                                acc[i][j] = fmaf(w2r[dy * 3 + 2], rv[j + 2], acc[i][j]);
                            }
                        }
                    }
                }
            }
        }
        __syncthreads();   // protect hs before next group overwrites it
    }

    float bb = b2s[0];
#pragma unroll
    for (int i = 0; i < 4; i++) {
        float4 o;
        o.x = acc[i][0] + bb;
        o.y = acc[i][1] + bb;
        o.z = acc[i][2] + bb;
        o.w = acc[i][3] + bb;
        *(float4*)(out + (size_t)(b * RR + ty0 + oy + i) * RR + tx0 + ox) = o;
    }
}

extern "C" void kernel_launch(void* const* d_in, const int* in_sizes, int n_in,
                              void* d_out, int out_size) {
    const float* yt = (const float*)d_in[0];
    const float* Ht = (const float*)d_in[1];
    const float* W1 = (const float*)d_in[2];
    const float* b1 = (const float*)d_in[3];
    const float* W2 = (const float*)d_in[4];
    const float* b2 = (const float*)d_in[5];
    float* out = (float*)d_out;

    // Immediate (non-stream) API: executes at call time, not captured.
    cudaFuncSetAttribute(conv_fused_kernel,
                         cudaFuncAttributeMaxDynamicSharedMemorySize, SMEM_BYTES);

    stage1_kernel<<<dim3(64, 8), 256>>>(yt, Ht);
    conv_fused_kernel<<<dim3(4, 4, 32), 256, SMEM_BYTES>>>(W1, b1, W2, b2, out);
}